// round 12
// baseline (speedup 1.0000x reference)
#include <cuda_runtime.h>
#include <cuda_bf16.h>
#include <cstdint>

// ---------------------------------------------------------------------------
// DispatchByVariable: grouped GEMM via mma.sync bf16 split (hi/lo, 3 MMAs)
//   x  : [8,4096,512] f32  (32768 tokens x 512)
//   W  : [8,512,512]  f32  (8 experts)
//   out[t] = x[t] @ W[bin(t)],  bin = sum(x[t,0] > {-1.5..1.5})
// R11 post-mortem: tensor capped ~57% by LDSM issue bandwidth (2 MMA/ldsm
//   at 64x32 warp tiles; LDSM floor 4cyc/SMSP ~ HMMA 2cyc/SMSP).
// R12: 64x64 warp tiles, 4 warps/CTA (128 thr), 6 MMA/ldsm, 255-reg budget.
// ---------------------------------------------------------------------------

#define NTOK 32768
#define DIM  512
#define NBIN 8
#define BM   128
#define BN   128
#define BKC  32
#define NCHUNK (DIM / BKC)                 // 16
#define PERM_CAP (NTOK + NBIN * BM)        // 33792
#define MAX_TILES_M (NTOK / BM + NBIN)     // 264
#define NSTAGE 3
#define NTBLK (NTOK / 256)                 // 128 token blocks
#define XHALF ((uint32_t)NTOK * DIM * 2)   // byte offset of x_lo half (32MB)
#define WHALF ((uint32_t)NBIN * DIM * DIM * 2)  // byte offset of w_lo half (4MB)

// ---------------- device scratch (no allocs) --------------------------------
__device__ int g_binof[NTOK];
__device__ int g_perm[PERM_CAP];
__device__ int g_hist[NTBLK][NBIN];
__device__ int g_offsets[NBIN + 1];
// merged hi|lo halves: [0, XHALF) = hi bytes, [XHALF, 2*XHALF) = lo bytes
__device__ __align__(256) __nv_bfloat16 g_x2[2u * NTOK * DIM];        // 64 MB
__device__ __align__(256) __nv_bfloat16 g_w2[2u * NBIN * DIM * DIM];  // 8 MB, K-major [e][n][k]

// ---------------- smem layout for GEMM (dynamic) -----------------------------
#define SM_ROWID 0            // 128 ints
#define SM_TILES 1024
#define STAGE_BYTES 32768     // A 16KB + B 16KB
#define SM_TOTAL (SM_TILES + NSTAGE * STAGE_BYTES)   // 99328 -> 2 CTAs/SM

// ---------------- PTX helpers ------------------------------------------------
__device__ __forceinline__ uint32_t smem_u32(const void* p) {
    uint32_t a;
    asm("{ .reg .u64 t; cvta.to.shared.u64 t, %1; cvt.u32.u64 %0, t; }"
        : "=r"(a) : "l"(p));
    return a;
}
__device__ __forceinline__ uint32_t sw128(uint32_t b) { return b ^ ((b >> 3) & 0x70); }

__device__ __forceinline__ void cp16(uint32_t d, const void* s) {
    asm volatile("cp.async.cg.shared.global [%0], [%1], 16;" :: "r"(d), "l"(s));
}
__device__ __forceinline__ void cp_commit() { asm volatile("cp.async.commit_group;"); }
__device__ __forceinline__ void cp_wait1()  { asm volatile("cp.async.wait_group 1;"); }
__device__ __forceinline__ void cp_wait0()  { asm volatile("cp.async.wait_group 0;"); }

__device__ __forceinline__ void ldsm4(uint32_t* r, uint32_t a) {
    asm volatile("ldmatrix.sync.aligned.m8n8.x4.shared.b16 {%0,%1,%2,%3}, [%4];"
                 : "=r"(r[0]), "=r"(r[1]), "=r"(r[2]), "=r"(r[3]) : "r"(a));
}
__device__ __forceinline__ void mma16816(float* c, const uint32_t* a,
                                         const uint32_t* b0) {
    asm volatile(
        "mma.sync.aligned.m16n8k16.row.col.f32.bf16.bf16.f32 "
        "{%0,%1,%2,%3},{%4,%5,%6,%7},{%8,%9},{%0,%1,%2,%3};"
        : "+f"(c[0]), "+f"(c[1]), "+f"(c[2]), "+f"(c[3])
        : "r"(a[0]), "r"(a[1]), "r"(a[2]), "r"(a[3]), "r"(b0[0]), "r"(b0[1]));
}
// B ldsm: x4 covers two n8 tiles (2bt, 2bt+1)
__device__ __forceinline__ void ldB(uint32_t addr, uint32_t Bf[8][2], int bt) {
    uint32_t r[4];
    ldsm4(r, addr);
    Bf[2 * bt][0] = r[0]; Bf[2 * bt][1] = r[2];
    Bf[2 * bt + 1][0] = r[1]; Bf[2 * bt + 1][1] = r[3];
}
// 8 independent MMAs: one m-tile x 8 n-tiles
__device__ __forceinline__ void mma_grp8(float acc[4][8][4], int mt,
                                         const uint32_t A[4],
                                         const uint32_t B[8][2]) {
#pragma unroll
    for (int nt = 0; nt < 8; nt++)
        mma16816(acc[mt][nt], A, B[nt]);
}

// ---------------- prep kernel 1: perm init + bucketize (smem hist) -----------
__global__ void k_prep(const float* __restrict__ x) {
    __shared__ int hist[NBIN];
    const int b = blockIdx.x, tid = threadIdx.x;
    const int i = b * 256 + tid;
    if (i < PERM_CAP) g_perm[i] = -1;
    if (b < NTBLK) {
        if (tid < NBIN) hist[tid] = 0;
        __syncthreads();
        float y = x[(size_t)i * DIM];
        int bin = 0;
        bin += (y > -1.5f); bin += (y > -1.0f); bin += (y > -0.5f); bin += (y > 0.0f);
        bin += (y >  0.5f); bin += (y >  1.0f); bin += (y >  1.5f);
        g_binof[i] = bin;
        atomicAdd(&hist[bin], 1);          // smem only
        __syncthreads();
        if (tid < NBIN) g_hist[b][tid] = hist[tid];
    }
}

// ---------------- prep kernel 2: deterministic scatter (no global atomics) ---
__global__ void k_scatter() {
    __shared__ int base[NBIN], totals[NBIN], offs[NBIN], cnt[NBIN];
    const int b = blockIdx.x, tid = threadIdx.x;
    if (tid < NBIN) {
        int pre = 0, tot = 0;
        for (int q = 0; q < NTBLK; q++) {
            int h = g_hist[q][tid];
            if (q < b) pre += h;
            tot += h;
        }
        base[tid] = pre; totals[tid] = tot; cnt[tid] = 0;
    }
    __syncthreads();
    if (tid == 0) {
        int off = 0;
        for (int k = 0; k < NBIN; k++) {
            offs[k] = off;
            if (b == 0) g_offsets[k] = off;
            off += ((totals[k] + BM - 1) / BM) * BM;
        }
        if (b == 0) g_offsets[NBIN] = off;
    }
    __syncthreads();
    const int t = b * 256 + tid;
    const int bin = g_binof[t];
    const int r = atomicAdd(&cnt[bin], 1);     // smem only
    g_perm[offs[bin] + base[bin] + r] = t;
}

// ---------------- fused convert: x -> hi/lo bf16, W -> transposed hi/lo ------
#define NXB (NTOK * DIM / 4 / 256)    // 16384 blocks for x
#define NWB (16 * 16 * NBIN)          // 2048 blocks for W
__global__ void k_convert(const float* __restrict__ x, const float* __restrict__ W) {
    __shared__ float t[32][33];
    const int b = blockIdx.x, tid = threadIdx.x;
    if (b < NXB) {
        int i = b * 256 + tid;                 // float4 index
        const uint32_t LOQ = XHALF / 4;        // lo half start, bf16x2 (4B) units
        float4 v = ((const float4*)x)[i];
        __nv_bfloat16 h0 = __float2bfloat16(v.x), h1 = __float2bfloat16(v.y);
        __nv_bfloat16 h2 = __float2bfloat16(v.z), h3 = __float2bfloat16(v.w);
        __nv_bfloat16 l0 = __float2bfloat16(v.x - __bfloat162float(h0));
        __nv_bfloat16 l1 = __float2bfloat16(v.y - __bfloat162float(h1));
        __nv_bfloat16 l2 = __float2bfloat16(v.z - __bfloat162float(h2));
        __nv_bfloat16 l3 = __float2bfloat16(v.w - __bfloat162float(h3));
        __nv_bfloat162 p;
        p.x = h0; p.y = h1; ((__nv_bfloat162*)g_x2)[2 * i]           = p;
        p.x = h2; p.y = h3; ((__nv_bfloat162*)g_x2)[2 * i + 1]       = p;
        p.x = l0; p.y = l1; ((__nv_bfloat162*)g_x2)[LOQ + 2 * i]     = p;
        p.x = l2; p.y = l3; ((__nv_bfloat162*)g_x2)[LOQ + 2 * i + 1] = p;
    } else {
        int w = b - NXB;
        int e = w >> 8;
        int k0 = ((w >> 4) & 15) * 32, nb = (w & 15) * 32;
        int tx = tid & 31, ty = tid >> 5;      // 32 x 8
        const float* Wb = W + (size_t)e * DIM * DIM;
#pragma unroll
        for (int i = 0; i < 4; i++)
            t[ty + i * 8][tx] = Wb[(size_t)(k0 + ty + i * 8) * DIM + nb + tx];
        __syncthreads();
        const uint32_t LOW = WHALF / 2;        // lo half start, bf16 elements
#pragma unroll
        for (int i = 0; i < 4; i++) {
            float v = t[tx][ty + i * 8];       // = W[e][k0+tx][nb+ty+i*8]
            __nv_bfloat16 h = __float2bfloat16(v);
            __nv_bfloat16 l = __float2bfloat16(v - __bfloat162float(h));
            size_t o = (size_t)e * DIM * DIM + (size_t)(nb + ty + i * 8) * DIM + (k0 + tx);
            g_w2[o] = h;
            g_w2[LOW + o] = l;
        }
    }
}

// ---------------- HMMA grouped GEMM: 4 warps, 64x64 warp tiles ----------------
__global__ __launch_bounds__(128, 2)
void k_gemm(float* __restrict__ out) {
    extern __shared__ char smem[];
    const int tid = threadIdx.x;
    const int total = g_offsets[NBIN];
    const int row0 = blockIdx.x * BM;
    if (row0 >= total) return;

    const uint32_t sb = smem_u32(smem);
    int* rowid_s = (int*)(smem + SM_ROWID);

    int bin = 0;
#pragma unroll
    for (int k = 1; k < NBIN; k++)
        if (row0 >= g_offsets[k]) bin = k;

    rowid_s[tid] = g_perm[row0 + tid];     // 128 threads, BM=128
    __syncthreads();

    const int n0 = blockIdx.y * BN;
    const uint32_t wrow0 = (uint32_t)bin * DIM + n0;   // W n-row base

    // --- load plumbing: thread covers rows (tid>>3)+16i, 16B chunk cc --------
    const int cc = tid & 7;
    const uint32_t hl16 = (uint32_t)(cc & 3) * 16;
    const uint32_t hsel = (cc < 4) ? 0u : 1u;
    const uint32_t dst0 = sw128((uint32_t)((tid >> 3) * 128) + (uint32_t)cc * 16);
    uint32_t offA[8];
#pragma unroll
    for (int i = 0; i < 8; i++) {
        int t = rowid_s[(tid >> 3) + 16 * i];
        if (t < 0) t = 0;
        offA[i] = (hsel ? XHALF : 0u) + (uint32_t)t * 1024u + hl16;
    }
    uint32_t offB = (hsel ? WHALF : 0u)
                  + (wrow0 + (uint32_t)(tid >> 3)) * 1024u + hl16;
    const char* const baseX = (const char*)g_x2;
    const char* const baseW = (const char*)g_w2;

    // smem dst strides: rows 16 apart => +2048 bytes, swizzle-exact
    // ((r+16)&7 == r&7 => same XOR field).
    auto loadA_half = [&](uint32_t ab, int h) {
#pragma unroll
        for (int i = 4 * h; i < 4 * h + 4; i++) {
            cp16(ab + dst0 + (uint32_t)i * 2048u, baseX + offA[i]);
            offA[i] += 64u;
        }
    };
    auto loadB = [&](uint32_t bb) {
#pragma unroll
        for (int i = 0; i < 8; i++)
            cp16(bb + dst0 + (uint32_t)i * 2048u, baseW + offB + (uint32_t)i * 16384u);
        offB += 64u;
    };

    {   // prologue: chunks 0 and 1
        uint32_t ab = sb + SM_TILES;
        loadA_half(ab, 0); loadA_half(ab, 1); loadB(ab + 16384); cp_commit();
        ab += STAGE_BYTES;
        loadA_half(ab, 0); loadA_half(ab, 1); loadB(ab + 16384); cp_commit();
    }

    const int lane = tid & 31;
    const int wid = tid >> 5;
    const int wm = (wid & 1) * 64;       // 2 warps in M
    const int wn = (wid >> 1) * 64;      // 2 warps in N
    const int lrow = lane & 15;
    const int lc16 = (lane >> 4) * 16;

    // ldsm base offsets; kk (^32) / lo (^64, ^96) via XOR (base bits 5,6 = 0).
    uint32_t aOff[4], bOff[4];
#pragma unroll
    for (int mt = 0; mt < 4; mt++)
        aOff[mt] = sw128((uint32_t)((wm + mt * 16 + lrow) * 128 + lc16));
#pragma unroll
    for (int bt = 0; bt < 4; bt++)
        bOff[bt] = sw128((uint32_t)((wn + bt * 16 + lrow) * 128 + lc16));

    float acc[4][8][4];
#pragma unroll
    for (int i = 0; i < 4; i++)
#pragma unroll
        for (int j = 0; j < 8; j++)
#pragma unroll
            for (int q = 0; q < 4; q++) acc[i][j][q] = 0.f;

    uint32_t Bh[8][2], Bl[8][2];
    uint32_t Ah[2][4], Al[2][4];         // ping-pong m-tile slots

#pragma unroll 1
    for (int c = 0; c < NCHUNK; c++) {
        if (c + 1 < NCHUNK) cp_wait1(); else cp_wait0();
        __syncthreads();                   // single barrier per chunk
        const uint32_t ab = sb + SM_TILES + (c % NSTAGE) * STAGE_BYTES;
        const uint32_t bb = ab + 16384;
        const bool pf = (c + 2 < NCHUNK);
        const uint32_t nab = sb + SM_TILES + ((c + 2) % NSTAGE) * STAGE_BYTES;

#pragma unroll
        for (int kk = 0; kk < 2; kk++) {
            const uint32_t d = kk * 32u;   // ^32 swizzle-exact
            // B frags: 8 n-tiles, hi+lo (8 ldsm)
#pragma unroll
            for (int bt = 0; bt < 4; bt++) {
                ldB(bb + (bOff[bt] ^ d),         Bh, bt);
                ldB(bb + (bOff[bt] ^ (d ^ 64u)), Bl, bt);
            }
            // A mt0, mt1
            ldsm4(Ah[0], ab + (aOff[0] ^ d)); ldsm4(Al[0], ab + (aOff[0] ^ (d ^ 64u)));
            ldsm4(Ah[1], ab + (aOff[1] ^ d)); ldsm4(Al[1], ab + (aOff[1] ^ (d ^ 64u)));
            // mt0: 24 MMAs
            mma_grp8(acc, 0, Ah[0], Bh);
            mma_grp8(acc, 0, Ah[0], Bl);
            if (pf && kk == 0) loadA_half(nab, 0);
            mma_grp8(acc, 0, Al[0], Bh);
            // refill slot 0 with mt2
            ldsm4(Ah[0], ab + (aOff[2] ^ d)); ldsm4(Al[0], ab + (aOff[2] ^ (d ^ 64u)));
            // mt1
            mma_grp8(acc, 1, Ah[1], Bh);
            if (pf && kk == 0) loadA_half(nab, 1);
            mma_grp8(acc, 1, Ah[1], Bl);
            mma_grp8(acc, 1, Al[1], Bh);
            // refill slot 1 with mt3
            ldsm4(Ah[1], ab + (aOff[3] ^ d)); ldsm4(Al[1], ab + (aOff[3] ^ (d ^ 64u)));
            // mt2
            mma_grp8(acc, 2, Ah[0], Bh);
            if (pf && kk == 0) { loadB(nab + 16384); cp_commit(); }
            mma_grp8(acc, 2, Ah[0], Bl);
            mma_grp8(acc, 2, Al[0], Bh);
            // mt3
            mma_grp8(acc, 3, Ah[1], Bh);
            mma_grp8(acc, 3, Ah[1], Bl);
            mma_grp8(acc, 3, Al[1], Bh);
        }
    }

    // epilogue: scatter acc to gmem through perm
    const int rq = lane >> 2;
    const int cq = (lane & 3) * 2;
#pragma unroll
    for (int mt = 0; mt < 4; mt++) {
        int rA = wm + mt * 16 + rq;
        int tA = rowid_s[rA];
        int tB = rowid_s[rA + 8];
#pragma unroll
        for (int nt = 0; nt < 8; nt++) {
            int col = n0 + wn + nt * 8 + cq;
            if (tA >= 0)
                *(float2*)(out + (size_t)tA * DIM + col) =
                    make_float2(acc[mt][nt][0], acc[mt][nt][1]);
            if (tB >= 0)
                *(float2*)(out + (size_t)tB * DIM + col) =
                    make_float2(acc[mt][nt][2], acc[mt][nt][3]);
        }
    }
}

// ---------------- launch --------------------------------------------------------
extern "C" void kernel_launch(void* const* d_in, const int* in_sizes, int n_in,
                              void* d_out, int out_size) {
    const float* x = (const float*)d_in[0];   // [8,4096,512] f32
    const float* W = (const float*)d_in[1];   // [8,512,512]  f32
    float* out = (float*)d_out;

    k_prep<<<(PERM_CAP + 255) / 256, 256>>>(x);
    k_scatter<<<NTBLK, 256>>>();
    k_convert<<<NXB + NWB, 256>>>(x, W);

    cudaFuncSetAttribute(k_gemm, cudaFuncAttributeMaxDynamicSharedMemorySize, SM_TOTAL);
    k_gemm<<<dim3(MAX_TILES_M, DIM / BN), 128, SM_TOTAL>>>(out);
}

// round 13
// speedup vs baseline: 1.0651x; 1.0651x over previous
#include <cuda_runtime.h>
#include <cuda_bf16.h>
#include <cstdint>

// ---------------------------------------------------------------------------
// DispatchByVariable: grouped GEMM via mma.sync bf16 split (hi/lo, 3 MMAs)
//   x  : [8,4096,512] f32  (32768 tokens x 512)
//   W  : [8,512,512]  f32  (8 experts)
//   out[t] = x[t] @ W[bin(t)],  bin = sum(x[t,0] > {-1.5..1.5})
// R12 post-mortem: HMMA rt ~= 8 cyc/SMSP; tensor capped 57% by EXPOSED LDSM
//   LATENCY at every kk/chunk boundary (not ldsm bandwidth).
// R13: cross-kk fragment prefetch (Bh ping-pong + A-mt0 hi prefetched during
//   previous kk's MMAs; Bl/A-lo loads hidden behind leading MMA groups).
// ---------------------------------------------------------------------------

#define NTOK 32768
#define DIM  512
#define NBIN 8
#define BM   128
#define BN   128
#define BKC  32
#define NCHUNK (DIM / BKC)                 // 16
#define PERM_CAP (NTOK + NBIN * BM)        // 33792
#define MAX_TILES_M (NTOK / BM + NBIN)     // 264
#define NSTAGE 3
#define NTBLK (NTOK / 256)                 // 128 token blocks
#define XHALF ((uint32_t)NTOK * DIM * 2)   // byte offset of x_lo half (32MB)
#define WHALF ((uint32_t)NBIN * DIM * DIM * 2)  // byte offset of w_lo half (4MB)

// ---------------- device scratch (no allocs) --------------------------------
__device__ int g_binof[NTOK];
__device__ int g_perm[PERM_CAP];
__device__ int g_hist[NTBLK][NBIN];
__device__ int g_offsets[NBIN + 1];
// merged hi|lo halves: [0, XHALF) = hi bytes, [XHALF, 2*XHALF) = lo bytes
__device__ __align__(256) __nv_bfloat16 g_x2[2u * NTOK * DIM];        // 64 MB
__device__ __align__(256) __nv_bfloat16 g_w2[2u * NBIN * DIM * DIM];  // 8 MB, K-major [e][n][k]

// ---------------- smem layout for GEMM (dynamic) -----------------------------
#define SM_ROWID 0            // 128 ints
#define SM_TILES 1024
#define STAGE_BYTES 32768     // A 16KB + B 16KB
#define SM_TOTAL (SM_TILES + NSTAGE * STAGE_BYTES)   // 99328 -> 2 CTAs/SM

// ---------------- PTX helpers ------------------------------------------------
__device__ __forceinline__ uint32_t smem_u32(const void* p) {
    uint32_t a;
    asm("{ .reg .u64 t; cvta.to.shared.u64 t, %1; cvt.u32.u64 %0, t; }"
        : "=r"(a) : "l"(p));
    return a;
}
__device__ __forceinline__ uint32_t sw128(uint32_t b) { return b ^ ((b >> 3) & 0x70); }

__device__ __forceinline__ void cp16(uint32_t d, const void* s) {
    asm volatile("cp.async.cg.shared.global [%0], [%1], 16;" :: "r"(d), "l"(s));
}
__device__ __forceinline__ void cp_commit() { asm volatile("cp.async.commit_group;"); }
__device__ __forceinline__ void cp_wait1()  { asm volatile("cp.async.wait_group 1;"); }
__device__ __forceinline__ void cp_wait0()  { asm volatile("cp.async.wait_group 0;"); }

__device__ __forceinline__ void ldsm4(uint32_t* r, uint32_t a) {
    asm volatile("ldmatrix.sync.aligned.m8n8.x4.shared.b16 {%0,%1,%2,%3}, [%4];"
                 : "=r"(r[0]), "=r"(r[1]), "=r"(r[2]), "=r"(r[3]) : "r"(a));
}
__device__ __forceinline__ void mma16816(float* c, const uint32_t* a,
                                         const uint32_t* b0) {
    asm volatile(
        "mma.sync.aligned.m16n8k16.row.col.f32.bf16.bf16.f32 "
        "{%0,%1,%2,%3},{%4,%5,%6,%7},{%8,%9},{%0,%1,%2,%3};"
        : "+f"(c[0]), "+f"(c[1]), "+f"(c[2]), "+f"(c[3])
        : "r"(a[0]), "r"(a[1]), "r"(a[2]), "r"(a[3]), "r"(b0[0]), "r"(b0[1]));
}
// B ldsm: x4 covers two n8 tiles (2bt, 2bt+1)
__device__ __forceinline__ void ldB(uint32_t addr, uint32_t (&Bf)[8][2], int bt) {
    uint32_t r[4];
    ldsm4(r, addr);
    Bf[2 * bt][0] = r[0]; Bf[2 * bt][1] = r[2];
    Bf[2 * bt + 1][0] = r[1]; Bf[2 * bt + 1][1] = r[3];
}
// 8 independent MMAs: one m-tile x 8 n-tiles
__device__ __forceinline__ void mma_grp8(float (&acc)[4][8][4], int mt,
                                         const uint32_t (&A)[4],
                                         const uint32_t (&B)[8][2]) {
#pragma unroll
    for (int nt = 0; nt < 8; nt++)
        mma16816(acc[mt][nt], A, B[nt]);
}

// ---------------- prep kernel 1: perm init + bucketize (smem hist) -----------
__global__ void k_prep(const float* __restrict__ x) {
    __shared__ int hist[NBIN];
    const int b = blockIdx.x, tid = threadIdx.x;
    const int i = b * 256 + tid;
    if (i < PERM_CAP) g_perm[i] = -1;
    if (b < NTBLK) {
        if (tid < NBIN) hist[tid] = 0;
        __syncthreads();
        float y = x[(size_t)i * DIM];
        int bin = 0;
        bin += (y > -1.5f); bin += (y > -1.0f); bin += (y > -0.5f); bin += (y > 0.0f);
        bin += (y >  0.5f); bin += (y >  1.0f); bin += (y >  1.5f);
        g_binof[i] = bin;
        atomicAdd(&hist[bin], 1);          // smem only
        __syncthreads();
        if (tid < NBIN) g_hist[b][tid] = hist[tid];
    }
}

// ---------------- prep kernel 2: deterministic scatter (no global atomics) ---
__global__ void k_scatter() {
    __shared__ int base[NBIN], totals[NBIN], offs[NBIN], cnt[NBIN];
    const int b = blockIdx.x, tid = threadIdx.x;
    if (tid < NBIN) {
        int pre = 0, tot = 0;
        for (int q = 0; q < NTBLK; q++) {
            int h = g_hist[q][tid];
            if (q < b) pre += h;
            tot += h;
        }
        base[tid] = pre; totals[tid] = tot; cnt[tid] = 0;
    }
    __syncthreads();
    if (tid == 0) {
        int off = 0;
        for (int k = 0; k < NBIN; k++) {
            offs[k] = off;
            if (b == 0) g_offsets[k] = off;
            off += ((totals[k] + BM - 1) / BM) * BM;
        }
        if (b == 0) g_offsets[NBIN] = off;
    }
    __syncthreads();
    const int t = b * 256 + tid;
    const int bin = g_binof[t];
    const int r = atomicAdd(&cnt[bin], 1);     // smem only
    g_perm[offs[bin] + base[bin] + r] = t;
}

// ---------------- fused convert: x -> hi/lo bf16, W -> transposed hi/lo ------
#define NXB (NTOK * DIM / 4 / 256)    // 16384 blocks for x
#define NWB (16 * 16 * NBIN)          // 2048 blocks for W
__global__ void k_convert(const float* __restrict__ x, const float* __restrict__ W) {
    __shared__ float t[32][33];
    const int b = blockIdx.x, tid = threadIdx.x;
    if (b < NXB) {
        int i = b * 256 + tid;                 // float4 index
        const uint32_t LOQ = XHALF / 4;        // lo half start, bf16x2 (4B) units
        float4 v = ((const float4*)x)[i];
        __nv_bfloat16 h0 = __float2bfloat16(v.x), h1 = __float2bfloat16(v.y);
        __nv_bfloat16 h2 = __float2bfloat16(v.z), h3 = __float2bfloat16(v.w);
        __nv_bfloat16 l0 = __float2bfloat16(v.x - __bfloat162float(h0));
        __nv_bfloat16 l1 = __float2bfloat16(v.y - __bfloat162float(h1));
        __nv_bfloat16 l2 = __float2bfloat16(v.z - __bfloat162float(h2));
        __nv_bfloat16 l3 = __float2bfloat16(v.w - __bfloat162float(h3));
        __nv_bfloat162 p;
        p.x = h0; p.y = h1; ((__nv_bfloat162*)g_x2)[2 * i]           = p;
        p.x = h2; p.y = h3; ((__nv_bfloat162*)g_x2)[2 * i + 1]       = p;
        p.x = l0; p.y = l1; ((__nv_bfloat162*)g_x2)[LOQ + 2 * i]     = p;
        p.x = l2; p.y = l3; ((__nv_bfloat162*)g_x2)[LOQ + 2 * i + 1] = p;
    } else {
        int w = b - NXB;
        int e = w >> 8;
        int k0 = ((w >> 4) & 15) * 32, nb = (w & 15) * 32;
        int tx = tid & 31, ty = tid >> 5;      // 32 x 8
        const float* Wb = W + (size_t)e * DIM * DIM;
#pragma unroll
        for (int i = 0; i < 4; i++)
            t[ty + i * 8][tx] = Wb[(size_t)(k0 + ty + i * 8) * DIM + nb + tx];
        __syncthreads();
        const uint32_t LOW = WHALF / 2;        // lo half start, bf16 elements
#pragma unroll
        for (int i = 0; i < 4; i++) {
            float v = t[tx][ty + i * 8];       // = W[e][k0+tx][nb+ty+i*8]
            __nv_bfloat16 h = __float2bfloat16(v);
            __nv_bfloat16 l = __float2bfloat16(v - __bfloat162float(h));
            size_t o = (size_t)e * DIM * DIM + (size_t)(nb + ty + i * 8) * DIM + (k0 + tx);
            g_w2[o] = h;
            g_w2[LOW + o] = l;
        }
    }
}

// ---------------- HMMA grouped GEMM: 64x64 warp tiles + frag prefetch --------
__global__ __launch_bounds__(128, 2)
void k_gemm(float* __restrict__ out) {
    extern __shared__ char smem[];
    const int tid = threadIdx.x;
    const int total = g_offsets[NBIN];
    const int row0 = blockIdx.x * BM;
    if (row0 >= total) return;

    const uint32_t sb = smem_u32(smem);
    int* rowid_s = (int*)(smem + SM_ROWID);

    int bin = 0;
#pragma unroll
    for (int k = 1; k < NBIN; k++)
        if (row0 >= g_offsets[k]) bin = k;

    rowid_s[tid] = g_perm[row0 + tid];     // 128 threads, BM=128
    __syncthreads();

    const int n0 = blockIdx.y * BN;
    const uint32_t wrow0 = (uint32_t)bin * DIM + n0;

    // --- load plumbing: thread covers rows (tid>>3)+16i, 16B chunk cc --------
    const int cc = tid & 7;
    const uint32_t hl16 = (uint32_t)(cc & 3) * 16;
    const uint32_t hsel = (cc < 4) ? 0u : 1u;
    const uint32_t dst0 = sw128((uint32_t)((tid >> 3) * 128) + (uint32_t)cc * 16);
    uint32_t offA[8];
#pragma unroll
    for (int i = 0; i < 8; i++) {
        int t = rowid_s[(tid >> 3) + 16 * i];
        if (t < 0) t = 0;
        offA[i] = (hsel ? XHALF : 0u) + (uint32_t)t * 1024u + hl16;
    }
    uint32_t offB = (hsel ? WHALF : 0u)
                  + (wrow0 + (uint32_t)(tid >> 3)) * 1024u + hl16;
    const char* const baseX = (const char*)g_x2;
    const char* const baseW = (const char*)g_w2;

    auto loadA = [&](uint32_t ab) {
#pragma unroll
        for (int i = 0; i < 8; i++) {
            cp16(ab + dst0 + (uint32_t)i * 2048u, baseX + offA[i]);
            offA[i] += 64u;
        }
    };
    auto loadB = [&](uint32_t bb) {
#pragma unroll
        for (int i = 0; i < 8; i++)
            cp16(bb + dst0 + (uint32_t)i * 2048u, baseW + offB + (uint32_t)i * 16384u);
        offB += 64u;
    };

    {   // prologue: fill stages 0 and 1
        uint32_t ab = sb + SM_TILES;
        loadA(ab); loadB(ab + 16384); cp_commit();
        ab += STAGE_BYTES;
        loadA(ab); loadB(ab + 16384); cp_commit();
    }

    const int lane = tid & 31;
    const int wid = tid >> 5;
    const int wm = (wid & 1) * 64;       // 2 warps in M
    const int wn = (wid >> 1) * 64;      // 2 warps in N
    const int lrow = lane & 15;
    const int lc16 = (lane >> 4) * 16;

    // ldsm base offsets; kk (^32) / lo (^64, ^96) via XOR (pre-swizzle bits
    // 5,6 of base are 0 since lc16 <= 16).
    uint32_t aOff[4], bOff[4];
#pragma unroll
    for (int mt = 0; mt < 4; mt++)
        aOff[mt] = sw128((uint32_t)((wm + mt * 16 + lrow) * 128 + lc16));
#pragma unroll
    for (int bt = 0; bt < 4; bt++)
        bOff[bt] = sw128((uint32_t)((wn + bt * 16 + lrow) * 128 + lc16));

    float acc[4][8][4];
#pragma unroll
    for (int i = 0; i < 4; i++)
#pragma unroll
        for (int j = 0; j < 8; j++)
#pragma unroll
            for (int q = 0; q < 4; q++) acc[i][j][q] = 0.f;

    uint32_t BhA[8][2], BhB[8][2];   // Bh ping-pong (cur / prefetched-next)
    uint32_t Bl[8][2];               // Bl shared set (loaded at kk start)
    uint32_t Ah0[4], Al0[4], Ah1[4], Al1[4];  // A slots
    uint32_t AhP[4];                 // prefetched next-kk mt0 hi

    // one kk-step; BhC = current (prefetched), BhN = fill for next kk.
    // (p_ab, p_d) = next kk's stage base / kk-delta for prefetch.
    auto kk_body = [&](uint32_t ab, uint32_t bb, uint32_t d,
                       uint32_t p_ab, uint32_t p_d,
                       uint32_t (&BhC)[8][2], uint32_t (&BhN)[8][2],
                       bool docp, uint32_t cab) {
        const uint32_t dl = d ^ 64u;
        // upfront loads hidden behind mt0's 24 MMAs (AhP already resident)
        ldB(bb + (bOff[0] ^ dl), Bl, 0);
        ldB(bb + (bOff[1] ^ dl), Bl, 1);
        ldB(bb + (bOff[2] ^ dl), Bl, 2);
        ldB(bb + (bOff[3] ^ dl), Bl, 3);
        ldsm4(Al0, ab + (aOff[0] ^ dl));         // mt0 lo
        ldsm4(Ah1, ab + (aOff[1] ^ d));          // mt1 hi
        ldsm4(Al1, ab + (aOff[1] ^ dl));         // mt1 lo
        // mt0
        mma_grp8(acc, 0, AhP, BhC);
        mma_grp8(acc, 0, AhP, Bl);
        mma_grp8(acc, 0, Al0, BhC);
        ldsm4(Ah0, ab + (aOff[2] ^ d));          // s0 <- mt2
        ldsm4(Al0, ab + (aOff[2] ^ dl));
        if (docp) loadA(cab);
        // mt1
        mma_grp8(acc, 1, Ah1, BhC);
        mma_grp8(acc, 1, Ah1, Bl);
        mma_grp8(acc, 1, Al1, BhC);
        ldsm4(Ah1, ab + (aOff[3] ^ d));          // s1 <- mt3
        ldsm4(Al1, ab + (aOff[3] ^ dl));
        if (docp) { loadB(cab + 16384); cp_commit(); }
        // mt2
        mma_grp8(acc, 2, Ah0, BhC);
        mma_grp8(acc, 2, Ah0, Bl);
        mma_grp8(acc, 2, Al0, BhC);
        // prefetch next kk: Bh + A-mt0 hi
        {
            const uint32_t p_bb = p_ab + 16384u;
            ldB(p_bb + (bOff[0] ^ p_d), BhN, 0);
            ldB(p_bb + (bOff[1] ^ p_d), BhN, 1);
            ldB(p_bb + (bOff[2] ^ p_d), BhN, 2);
            ldB(p_bb + (bOff[3] ^ p_d), BhN, 3);
            ldsm4(AhP, p_ab + (aOff[0] ^ p_d));
        }
        // mt3
        mma_grp8(acc, 3, Ah1, BhC);
        mma_grp8(acc, 3, Ah1, Bl);
        mma_grp8(acc, 3, Al1, BhC);
    };

    // prime fragments for chunk 0 kk0 (stage 0 fill is complete after wait1)
    cp_wait1();
    __syncthreads();
    {
        const uint32_t ab = sb + SM_TILES, bb = ab + 16384;
        ldB(bb + bOff[0], BhA, 0); ldB(bb + bOff[1], BhA, 1);
        ldB(bb + bOff[2], BhA, 2); ldB(bb + bOff[3], BhA, 3);
        ldsm4(AhP, ab + aOff[0]);
    }

#pragma unroll 1
    for (int c = 0; c < NCHUNK; c++) {
        cp_wait0();                      // stages c and c+1 both resident
        __syncthreads();                 // single barrier per chunk
        const uint32_t ab = sb + SM_TILES + (c % NSTAGE) * STAGE_BYTES;
        const uint32_t bb = ab + 16384;
        const bool docp = (c + 2 < NCHUNK);
        const uint32_t cab = sb + SM_TILES + ((c + 2) % NSTAGE) * STAGE_BYTES;
        // next chunk's stage for kk1's prefetch (self if last chunk: harmless)
        const uint32_t nab = (c + 1 < NCHUNK)
            ? sb + SM_TILES + ((c + 1) % NSTAGE) * STAGE_BYTES : ab;

        kk_body(ab, bb, 0u,  ab,  32u, BhA, BhB, docp, cab);  // kk0
        kk_body(ab, bb, 32u, nab, 0u,  BhB, BhA, false, 0u);  // kk1
    }

    // epilogue: scatter acc to gmem through perm
    const int rq = lane >> 2;
    const int cq = (lane & 3) * 2;
#pragma unroll
    for (int mt = 0; mt < 4; mt++) {
        int rA = wm + mt * 16 + rq;
        int tA = rowid_s[rA];
        int tB = rowid_s[rA + 8];
#pragma unroll
        for (int nt = 0; nt < 8; nt++) {
            int col = n0 + wn + nt * 8 + cq;
            if (tA >= 0)
                *(float2*)(out + (size_t)tA * DIM + col) =
                    make_float2(acc[mt][nt][0], acc[mt][nt][1]);
            if (tB >= 0)
                *(float2*)(out + (size_t)tB * DIM + col) =
                    make_float2(acc[mt][nt][2], acc[mt][nt][3]);
        }
    }
}

// ---------------- launch --------------------------------------------------------
extern "C" void kernel_launch(void* const* d_in, const int* in_sizes, int n_in,
                              void* d_out, int out_size) {
    const float* x = (const float*)d_in[0];   // [8,4096,512] f32
    const float* W = (const float*)d_in[1];   // [8,512,512]  f32
    float* out = (float*)d_out;

    k_prep<<<(PERM_CAP + 255) / 256, 256>>>(x);
    k_scatter<<<NTBLK, 256>>>();
    k_convert<<<NXB + NWB, 256>>>(x, W);

    cudaFuncSetAttribute(k_gemm, cudaFuncAttributeMaxDynamicSharedMemorySize, SM_TOTAL);
    k_gemm<<<dim3(MAX_TILES_M, DIM / BN), 128, SM_TOTAL>>>(out);
}